// round 15
// baseline (speedup 1.0000x reference)
#include <cuda_runtime.h>
#include <cuda_bf16.h>

#define BB 2
#define DD 10
#define HH 512
#define WW 512
#define HW (HH * WW)

__device__ __forceinline__ float4 fmax4(float4 a, float4 b) {
    return make_float4(fmaxf(a.x, b.x), fmaxf(a.y, b.y), fmaxf(a.z, b.z), fmaxf(a.w, b.w));
}

// component jj of quad
__device__ __forceinline__ float selB(float4 v, int jj) {
    float r = v.x;
    r = (jj == 1) ? v.y : r;
    r = (jj == 2) ? v.z : r;
    r = (jj == 3) ? v.w : r;
    return r;
}
// value at wq-1: component jj-1 for jj>=1, else edge scalar e
__device__ __forceinline__ float selA(float4 v, float e, int jj) {
    float r = e;
    r = (jj == 1) ? v.x : r;
    r = (jj == 2) ? v.y : r;
    r = (jj == 3) ? v.z : r;
    return r;
}
// value at wq+1: component jj+1 for jj<=2, else edge scalar e
__device__ __forceinline__ float selC(float4 v, float e, int jj) {
    float r = v.y;
    r = (jj == 1) ? v.z : r;
    r = (jj == 2) ? v.w : r;
    r = (jj == 3) ? e   : r;
    return r;
}

__global__ __launch_bounds__(256, 4)   // 4 CTAs/SM (5th CTA proven neutral in R14)
void quadinterp3d_kernel(const float* __restrict__ x, float* __restrict__ out) {
    // Block = 2 complete W-rows (tid 0-127: h0, tid 128-255: h0+1); same (b,d) per block.
    __shared__ float sCmX[256], sCmW[256], sV4X[256], sV4W[256];
    __shared__ unsigned short q[512];    // (tid<<2 | j) codes of detected maxima
    __shared__ int qcnt;
    __shared__ float2 sDg[1024];         // per-code handoff: (e0+e8-e6-e2, row4 edge value)

    const int tid  = threadIdx.x;
    const int gid  = blockIdx.x * 256 + tid;
    const int lane = tid & 31;
    const int w4 = gid & 127;
    const int h  = (gid >> 7) & 511;
    const int t  = gid >> 16;            // 0..19 (B*D)
    const int d  = t % DD;
    const int b  = t / DD;
    const int w0 = w4 << 2;

    if (tid == 0) qcnt = 0;

    const int off4 = (d * HH + h) * WW;
    const float* __restrict__ base = x + (size_t)b * DD * HW;
    const float* __restrict__ pc = base + off4 + w0;

    // Clamped row deltas (replicate padding); dzm/dzp uniform per block
    const int dym = (h > 0)      ? WW : 0;
    const int dyp = (h < HH - 1) ? WW : 0;
    const int dzm = (d > 0)      ? HW : 0;
    const int dzp = (d < DD - 1) ? HW : 0;

    // Batched independent loads: one aligned float4 per stencil row (MLP=9)
    float4 v0 = *reinterpret_cast<const float4*>(pc - dzm - dym);
    float4 v1 = *reinterpret_cast<const float4*>(pc - dzm);
    float4 v2 = *reinterpret_cast<const float4*>(pc - dzm + dyp);
    float4 v3 = *reinterpret_cast<const float4*>(pc - dym);
    float4 v4 = *reinterpret_cast<const float4*>(pc);
    float4 v5 = *reinterpret_cast<const float4*>(pc + dyp);
    float4 v6 = *reinterpret_cast<const float4*>(pc + dzp - dym);
    float4 v7 = *reinterpret_cast<const float4*>(pc + dzp);
    float4 v8 = *reinterpret_cast<const float4*>(pc + dzp + dyp);

    // Column max of the 8 non-center rows
    float4 cm = fmax4(fmax4(v0, v1), fmax4(v2, v3));
    cm = fmax4(cm, fmax4(fmax4(v5, v6), fmax4(v7, v8)));

    // Block-level edge exchange
    sCmX[tid] = cm.x;  sCmW[tid] = cm.w;
    sV4X[tid] = v4.x;  sV4W[tid] = v4.w;
    __syncthreads();

    const bool atL = (w4 == 0);
    const bool atR = (w4 == 127);
    const float cmL = atL ? cm.x : sCmW[tid - 1];
    const float cmR = atR ? cm.w : sCmX[tid + 1];
    const float u0  = atL ? v4.x : sV4W[tid - 1];
    const float u5  = atR ? v4.w : sV4X[tid + 1];

    // Windowed max over [cmL, cm.x, cm.y, cm.z, cm.w, cmR]
    const float win0 = fmaxf(fmaxf(cmL,  cm.x), cm.y);
    const float win1 = fmaxf(fmaxf(cm.x, cm.y), cm.z);
    const float win2 = fmaxf(fmaxf(cm.y, cm.z), cm.w);
    const float win3 = fmaxf(fmaxf(cm.z, cm.w), cmR);

    // Strict-local-max mask (center row excludes the center element)
    const float nm0 = fmaxf(fmaxf(win0, fmaxf(u0,   v4.y)), 0.0f);
    const float nm1 = fmaxf(fmaxf(win1, fmaxf(v4.x, v4.z)), 0.0f);
    const float nm2 = fmaxf(fmaxf(win2, fmaxf(v4.y, v4.w)), 0.0f);
    const float nm3 = fmaxf(fmaxf(win3, fmaxf(v4.z, u5)),   0.0f);

    const bool m0 = v4.x > nm0;
    const bool m1 = v4.y > nm1;
    const bool m2 = v4.z > nm2;
    const bool m3 = v4.w > nm3;

    // ---- Owner handoff for maxima: the 4 diagonal values (components jj of
    //      v0,v2,v6,v8) and the row-4 edge (u0/u5) are already in registers —
    //      combine and stage them so the queue phase needn't re-load them. ----
    if (m0) sDg[(tid << 2) | 0] = make_float2(v0.x + v8.x - v6.x - v2.x, u0);
    if (m1) sDg[(tid << 2) | 1] = make_float2(v0.y + v8.y - v6.y - v2.y, 0.0f);
    if (m2) sDg[(tid << 2) | 2] = make_float2(v0.z + v8.z - v6.z - v2.z, 0.0f);
    if (m3) sDg[(tid << 2) | 3] = make_float2(v0.w + v8.w - v6.w - v2.w, u5);

    // ---- Default stores FIRST (coords = grid, y = x). Queue phase (ordered by
    //      the __syncthreads below) overwrites the maxima entries. ----
    const size_t plsz = (size_t)DD * HW;
    const size_t inner = (size_t)off4 + w0;
    const float fd = (float)d, fh = (float)h, fw = (float)w0;
    *reinterpret_cast<float4*>(out + (size_t)(b * 3 + 0) * plsz + inner) =
        make_float4(fd, fd, fd, fd);
    *reinterpret_cast<float4*>(out + (size_t)(b * 3 + 1) * plsz + inner) =
        make_float4(fh, fh, fh, fh);
    *reinterpret_cast<float4*>(out + (size_t)(b * 3 + 2) * plsz + inner) =
        make_float4(fw, fw + 1.0f, fw + 2.0f, fw + 3.0f);
    *reinterpret_cast<float4*>(out + (size_t)BB * 3 * plsz + (size_t)b * plsz + inner) = v4;

    // ---- Warp-aggregated queue push: one shared atomic per warp ----
    const unsigned bal0 = __ballot_sync(0xffffffffu, m0);
    const unsigned bal1 = __ballot_sync(0xffffffffu, m1);
    const unsigned bal2 = __ballot_sync(0xffffffffu, m2);
    const unsigned bal3 = __ballot_sync(0xffffffffu, m3);
    const int nWarp = __popc(bal0) + __popc(bal1) + __popc(bal2) + __popc(bal3);
    int basei = 0;
    if (lane == 0 && nWarp) basei = atomicAdd(&qcnt, nWarp);
    basei = __shfl_sync(0xffffffffu, basei, 0);
    {
        const unsigned lm = (1u << lane) - 1u;
        int p = 0;
        if (m0) q[basei + __popc(bal0 & lm)] = (unsigned short)((tid << 2) | 0);
        p += __popc(bal0);
        if (m1) q[basei + p + __popc(bal1 & lm)] = (unsigned short)((tid << 2) | 1);
        p += __popc(bal1);
        if (m2) q[basei + p + __popc(bal2 & lm)] = (unsigned short)((tid << 2) | 2);
        p += __popc(bal2);
        if (m3) q[basei + p + __popc(bal3 & lm)] = (unsigned short)((tid << 2) | 3);
    }
    __syncthreads();

    // ---- Dense queue processing: one thread per maximum, direct scattered stores.
    //      Gather: 5 aligned LDG.128 + staged handoff (diag sum + row4 edge)
    //      + 4 edge scalars only when jj==0/3. ----
    const int cnt = qcnt;
    for (int i = tid; i < cnt; i += 256) {
        const int code = q[i];
        const int jj   = code & 3;
        const int otid = code >> 2;
        const int wq   = (((otid & 127) << 2) | jj);
        const int hq   = (blockIdx.x * 2 + (otid >> 7)) & 511;
        const int wb   = wq & ~3;                       // aligned quad base

        const float* __restrict__ rowc = base + (d * HH + hq) * WW;
        const int qym = (hq > 0)      ? WW : 0;
        const int qyp = (hq < HH - 1) ? WW : 0;

        // 5 aligned quads (mid rows) — each contains [wq-1, wq, wq+1] when jj is 1 or 2
        const float4 Q4 = *reinterpret_cast<const float4*>(rowc + wb);
        const float4 Q3 = *reinterpret_cast<const float4*>(rowc - qym + wb);
        const float4 Q5 = *reinterpret_cast<const float4*>(rowc + qyp + wb);
        const float4 Q1 = *reinterpret_cast<const float4*>(rowc - dzm + wb);
        const float4 Q7 = *reinterpret_cast<const float4*>(rowc + dzp + wb);

        // Staged handoff: diag combination + row-4 edge value
        const float2 dg = sDg[code];

        // Edge scalars (rows 1,3,5,7 one column outside the quad), only jj==0/3
        const bool eLz = (jj == 0), eRz = (jj == 3);
        float x3 = 0.f, x5 = 0.f, x1 = 0.f, x7 = 0.f;
        if (eLz | eRz) {
            const int we = eLz ? (wq + ((wq > 0) ? -1 : 0))
                               : (wq + ((wq < WW - 1) ? 1 : 0));
            x3 = __ldg(rowc - qym + we);
            x5 = __ldg(rowc + qyp + we);
            x1 = __ldg(rowc - dzm + we);
            x7 = __ldg(rowc + dzp + we);
        }

        const float cc = selB(Q4, jj), a4 = selA(Q4, dg.y, jj), c4 = selC(Q4, dg.y, jj);
        const float b3 = selB(Q3, jj), a3 = selA(Q3, x3, jj), c3 = selC(Q3, x3, jj);
        const float b5 = selB(Q5, jj), a5 = selA(Q5, x5, jj), c5 = selC(Q5, x5, jj);
        const float b1 = selB(Q1, jj), a1 = selA(Q1, x1, jj), c1 = selC(Q1, x1, jj);
        const float b7 = selB(Q7, jj), a7 = selA(Q7, x7, jj), c7 = selC(Q7, x7, jj);

        // Newton solve (same algebra as the verified kernels; H symmetric)
        const float gx = 0.5f * (c4 - a4);
        const float gy = 0.5f * (b5 - b3);
        const float gs = 0.5f * (b7 - b1);

        const float h00 = a4 + c4 - 2.0f * cc;
        const float h11 = b3 + b5 - 2.0f * cc;
        const float h22 = b1 + b7 - 2.0f * cc;
        const float h01 = 0.25f * (a3 + c5 - a5 - c3);
        const float h12 = 0.25f * dg.x;
        const float h02 = 0.25f * (a1 + c7 - a7 - c1);

        const float c00 = h11 * h22 - h12 * h12;
        const float c01 = h01 * h22 - h12 * h02;
        const float c02 = h01 * h12 - h11 * h02;
        const float det = h00 * c00 - h01 * c01 + h02 * c02;

        const float t1 = gy * h22 - h12 * gs;
        const float t2 = gy * h12 - h11 * gs;
        const float t3 = h01 * gs - gy * h02;

        const float inv = 1.0f / det;
        const float sx = (gx * c00 - h01 * t1 + h02 * t2) * inv;
        const float sy = (h00 * t1 - gx * c01 + h02 * t3) * inv;
        const float ss = (h00 * (h11 * gs - h12 * gy) - h01 * t3 + gx * c02) * inv;

        float d0 = -sx, d1 = -sy, d2 = -ss;
        const float far = fmaxf(fmaxf(fabsf(d0), fabsf(d1)), fabsf(d2));
        if (far > 0.7f) { d0 = 0.0f; d1 = 0.0f; d2 = 0.0f; }

        const float ry = cc + 0.5f * (gx * d0 + gy * d1 + gs * d2) + 10.0f;

        const size_t innq = (size_t)(d * HH + hq) * WW + wq;
        out[(size_t)(b * 3 + 0) * plsz + innq] = (float)d  + d2;
        out[(size_t)(b * 3 + 1) * plsz + innq] = (float)hq + d1;
        out[(size_t)(b * 3 + 2) * plsz + innq] = (float)wq + d0;
        out[(size_t)BB * 3 * plsz + (size_t)b * plsz + innq] = ry;
    }
}

extern "C" void kernel_launch(void* const* d_in, const int* in_sizes, int n_in,
                              void* d_out, int out_size) {
    const float* x = (const float*)d_in[0];
    float* out = (float*)d_out;
    const int total_threads = BB * DD * HH * (WW / 4);   // 1,310,720
    const int block = 256;
    const int grid = total_threads / block;              // 5,120
    quadinterp3d_kernel<<<grid, block>>>(x, out);
}

// round 16
// speedup vs baseline: 1.0805x; 1.0805x over previous
#include <cuda_runtime.h>
#include <cuda_bf16.h>

#define BB 2
#define DD 10
#define HH 512
#define WW 512
#define HW (HH * WW)

__device__ __forceinline__ float4 fmax4(float4 a, float4 b) {
    return make_float4(fmaxf(a.x, b.x), fmaxf(a.y, b.y), fmaxf(a.z, b.z), fmaxf(a.w, b.w));
}

// component jj of quad
__device__ __forceinline__ float selB(float4 v, int jj) {
    float r = v.x;
    r = (jj == 1) ? v.y : r;
    r = (jj == 2) ? v.z : r;
    r = (jj == 3) ? v.w : r;
    return r;
}
// value at wq-1: component jj-1 for jj>=1, else edge scalar e
__device__ __forceinline__ float selA(float4 v, float e, int jj) {
    float r = e;
    r = (jj == 1) ? v.x : r;
    r = (jj == 2) ? v.y : r;
    r = (jj == 3) ? v.z : r;
    return r;
}
// value at wq+1: component jj+1 for jj<=2, else edge scalar e
__device__ __forceinline__ float selC(float4 v, float e, int jj) {
    float r = v.y;
    r = (jj == 1) ? v.z : r;
    r = (jj == 2) ? v.w : r;
    r = (jj == 3) ? e   : r;
    return r;
}

__global__ __launch_bounds__(256, 4)   // 64-reg cap, 4 CTAs/SM
void quadinterp3d_kernel(const float* __restrict__ x, float* __restrict__ out) {
    // Each thread covers 2 vertically-adjacent voxel-quads (8 voxels).
    // Block = 256 threads = 2 h-pairs x 128 w4  -> covers 4 h-rows x 512 w.
    __shared__ float4 sEw[256], sEx[256];   // edge exchange: {cm0,cm1,v4a,v4b} w/x comps
    __shared__ unsigned short q[1024];      // (tid<<3 | hsel<<2 | jj) codes
    __shared__ int qcnt;

    const int tid  = threadIdx.x;
    const int gid  = blockIdx.x * 256 + tid;
    const int lane = tid & 31;
    const int w4    = gid & 127;
    const int hpair = (gid >> 7) & 255;      // 0..255 per (b,d)
    const int t     = gid >> 15;             // 0..19 (B*D)
    const int d = t % DD;
    const int b = t / DD;
    const int h  = hpair << 1;               // even, 0..510 (covers h, h+1)
    const int w0 = w4 << 2;

    if (tid == 0) qcnt = 0;

    const int off4 = (d * HH + h) * WW;
    const float* __restrict__ base = x + (size_t)b * DD * HW;
    const float* __restrict__ pc = base + off4 + w0;

    // Clamped row offsets relative to row h (replicate padding)
    const int dym   = (h > 0) ? WW : 0;                 // h-1
    const int rofs2 = WW + ((h < HH - 2) ? WW : 0);     // h+2 (clamped to h+1 at top edge)
    const int dzm = (d > 0)      ? HW : 0;
    const int dzp = (d < DD - 1) ? HW : 0;

    // 12 independent LDG.128: planes (zm, d, zp) x rows (h-1, h, h+1, h+2)
    const float4 a0 = *reinterpret_cast<const float4*>(pc - dzm - dym);
    const float4 a1 = *reinterpret_cast<const float4*>(pc - dzm);
    const float4 a2 = *reinterpret_cast<const float4*>(pc - dzm + WW);
    const float4 a3 = *reinterpret_cast<const float4*>(pc - dzm + rofs2);
    const float4 b0 = *reinterpret_cast<const float4*>(pc - dym);
    const float4 b1 = *reinterpret_cast<const float4*>(pc);
    const float4 b2 = *reinterpret_cast<const float4*>(pc + WW);
    const float4 b3 = *reinterpret_cast<const float4*>(pc + rofs2);
    const float4 c0 = *reinterpret_cast<const float4*>(pc + dzp - dym);
    const float4 c1 = *reinterpret_cast<const float4*>(pc + dzp);
    const float4 c2 = *reinterpret_cast<const float4*>(pc + dzp + WW);
    const float4 c3 = *reinterpret_cast<const float4*>(pc + dzp + rofs2);

    // Shared partial maxima between the two rows' 26-neighbor trees
    const float4 B0 = fmax4(a1, c1);                   // non-center planes, row h
    const float4 B1 = fmax4(a2, c2);                   // non-center planes, row h+1
    const float4 A  = fmax4(fmax4(a0, c0), b0);        // all planes, row h-1
    const float4 C  = fmax4(fmax4(a3, c3), b3);        // all planes, row h+2
    const float4 cm0 = fmax4(fmax4(A, B0), fmax4(B1, b2));  // excl center (d,h)
    const float4 cm1 = fmax4(fmax4(B0, b1), fmax4(B1, C));  // excl center (d,h+1)

    // Block-level edge exchange (both rows + both centers, packed)
    sEw[tid] = make_float4(cm0.w, cm1.w, b1.w, b2.w);
    sEx[tid] = make_float4(cm0.x, cm1.x, b1.x, b2.x);
    __syncthreads();

    const bool atL = (w4 == 0);
    const bool atR = (w4 == 127);
    const float4 Lv = atL ? make_float4(cm0.x, cm1.x, b1.x, b2.x) : sEw[tid - 1];
    const float4 Rv = atR ? make_float4(cm0.w, cm1.w, b1.w, b2.w) : sEx[tid + 1];
    // Lv = {cm0L, cm1L, u0a, u0b},  Rv = {cm0R, cm1R, u5a, u5b}

    // ---- Row h mask ----
    const float w00 = fmaxf(fmaxf(Lv.x,  cm0.x), cm0.y);
    const float w01 = fmaxf(fmaxf(cm0.x, cm0.y), cm0.z);
    const float w02 = fmaxf(fmaxf(cm0.y, cm0.z), cm0.w);
    const float w03 = fmaxf(fmaxf(cm0.z, cm0.w), Rv.x);
    const float n00 = fmaxf(fmaxf(w00, fmaxf(Lv.z, b1.y)), 0.0f);
    const float n01 = fmaxf(fmaxf(w01, fmaxf(b1.x, b1.z)), 0.0f);
    const float n02 = fmaxf(fmaxf(w02, fmaxf(b1.y, b1.w)), 0.0f);
    const float n03 = fmaxf(fmaxf(w03, fmaxf(b1.z, Rv.z)), 0.0f);
    const bool m00 = b1.x > n00, m01 = b1.y > n01, m02 = b1.z > n02, m03 = b1.w > n03;

    // ---- Row h+1 mask ----
    const float w10 = fmaxf(fmaxf(Lv.y,  cm1.x), cm1.y);
    const float w11 = fmaxf(fmaxf(cm1.x, cm1.y), cm1.z);
    const float w12 = fmaxf(fmaxf(cm1.y, cm1.z), cm1.w);
    const float w13 = fmaxf(fmaxf(cm1.z, cm1.w), Rv.y);
    const float n10 = fmaxf(fmaxf(w10, fmaxf(Lv.w, b2.y)), 0.0f);
    const float n11 = fmaxf(fmaxf(w11, fmaxf(b2.x, b2.z)), 0.0f);
    const float n12 = fmaxf(fmaxf(w12, fmaxf(b2.y, b2.w)), 0.0f);
    const float n13 = fmaxf(fmaxf(w13, fmaxf(b2.z, Rv.w)), 0.0f);
    const bool m10 = b2.x > n10, m11 = b2.y > n11, m12 = b2.z > n12, m13 = b2.w > n13;

    // ---- Default stores FIRST (coords = grid, y = x); queue overwrites maxima. ----
    const size_t plsz = (size_t)DD * HW;
    const size_t in0 = (size_t)off4 + w0;
    const size_t in1 = in0 + WW;
    const float fd = (float)d, fh = (float)h, fw = (float)w0;
    float* const o0 = out + (size_t)(b * 3 + 0) * plsz;
    float* const o1 = out + (size_t)(b * 3 + 1) * plsz;
    float* const o2 = out + (size_t)(b * 3 + 2) * plsz;
    float* const oy = out + (size_t)BB * 3 * plsz + (size_t)b * plsz;
    *reinterpret_cast<float4*>(o0 + in0) = make_float4(fd, fd, fd, fd);
    *reinterpret_cast<float4*>(o0 + in1) = make_float4(fd, fd, fd, fd);
    *reinterpret_cast<float4*>(o1 + in0) = make_float4(fh, fh, fh, fh);
    *reinterpret_cast<float4*>(o1 + in1) = make_float4(fh + 1.0f, fh + 1.0f, fh + 1.0f, fh + 1.0f);
    *reinterpret_cast<float4*>(o2 + in0) = make_float4(fw, fw + 1.0f, fw + 2.0f, fw + 3.0f);
    *reinterpret_cast<float4*>(o2 + in1) = make_float4(fw, fw + 1.0f, fw + 2.0f, fw + 3.0f);
    *reinterpret_cast<float4*>(oy + in0) = b1;
    *reinterpret_cast<float4*>(oy + in1) = b2;

    // ---- Warp-aggregated queue push (8 ballots, one shared atomic per warp) ----
    const unsigned bl[8] = {
        __ballot_sync(0xffffffffu, m00), __ballot_sync(0xffffffffu, m01),
        __ballot_sync(0xffffffffu, m02), __ballot_sync(0xffffffffu, m03),
        __ballot_sync(0xffffffffu, m10), __ballot_sync(0xffffffffu, m11),
        __ballot_sync(0xffffffffu, m12), __ballot_sync(0xffffffffu, m13)
    };
    const bool mk[8] = {m00, m01, m02, m03, m10, m11, m12, m13};
    int nWarp = 0;
    #pragma unroll
    for (int k = 0; k < 8; k++) nWarp += __popc(bl[k]);
    int basei = 0;
    if (lane == 0 && nWarp) basei = atomicAdd(&qcnt, nWarp);
    basei = __shfl_sync(0xffffffffu, basei, 0);
    {
        const unsigned lm = (1u << lane) - 1u;
        int p = 0;
        #pragma unroll
        for (int k = 0; k < 8; k++) {
            if (mk[k]) q[basei + p + __popc(bl[k] & lm)] = (unsigned short)((tid << 3) | k);
            p += __popc(bl[k]);
        }
    }
    __syncthreads();

    // ---- Dense queue processing (one thread per maximum), R13-style vectorized gather ----
    const int blk_in = blockIdx.x & 127;     // block's h-group within (b,d)
    const int cnt = qcnt;
    for (int i = tid; i < cnt; i += 256) {
        const int code = q[i];
        const int jj   = code & 3;
        const int hsel = (code >> 2) & 1;
        const int otid = code >> 3;
        const int wq   = (((otid & 127) << 2) | jj);
        const int hq   = (blk_in << 2) + ((otid >> 7) << 1) + hsel;   // 0..511
        const int wb   = wq & ~3;

        const float* __restrict__ rowc = base + (d * HH + hq) * WW;
        const int qym = (hq > 0)      ? WW : 0;
        const int qyp = (hq < HH - 1) ? WW : 0;

        const float4 Q4 = *reinterpret_cast<const float4*>(rowc + wb);
        const float4 Q3 = *reinterpret_cast<const float4*>(rowc - qym + wb);
        const float4 Q5 = *reinterpret_cast<const float4*>(rowc + qyp + wb);
        const float4 Q1 = *reinterpret_cast<const float4*>(rowc - dzm + wb);
        const float4 Q7 = *reinterpret_cast<const float4*>(rowc + dzp + wb);

        const float e0 = __ldg(rowc - dzm - qym + wq);
        const float e2 = __ldg(rowc - dzm + qyp + wq);
        const float e6 = __ldg(rowc + dzp - qym + wq);
        const float e8 = __ldg(rowc + dzp + qyp + wq);

        const bool eLz = (jj == 0), eRz = (jj == 3);
        float x4 = 0.f, x3 = 0.f, x5 = 0.f, x1 = 0.f, x7 = 0.f;
        if (eLz | eRz) {
            const int we = eLz ? (wq + ((wq > 0) ? -1 : 0))
                               : (wq + ((wq < WW - 1) ? 1 : 0));
            x4 = __ldg(rowc + we);
            x3 = __ldg(rowc - qym + we);
            x5 = __ldg(rowc + qyp + we);
            x1 = __ldg(rowc - dzm + we);
            x7 = __ldg(rowc + dzp + we);
        }

        const float cc = selB(Q4, jj), a4 = selA(Q4, x4, jj), c4 = selC(Q4, x4, jj);
        const float b3v = selB(Q3, jj), a3v = selA(Q3, x3, jj), c3v = selC(Q3, x3, jj);
        const float b5v = selB(Q5, jj), a5v = selA(Q5, x5, jj), c5v = selC(Q5, x5, jj);
        const float b1v = selB(Q1, jj), a1v = selA(Q1, x1, jj), c1v = selC(Q1, x1, jj);
        const float b7v = selB(Q7, jj), a7v = selA(Q7, x7, jj), c7v = selC(Q7, x7, jj);

        // Newton solve (same algebra as the verified kernels; H symmetric)
        const float gx = 0.5f * (c4 - a4);
        const float gy = 0.5f * (b5v - b3v);
        const float gs = 0.5f * (b7v - b1v);

        const float h00 = a4 + c4 - 2.0f * cc;
        const float h11 = b3v + b5v - 2.0f * cc;
        const float h22 = b1v + b7v - 2.0f * cc;
        const float h01 = 0.25f * (a3v + c5v - a5v - c3v);
        const float h12 = 0.25f * (e0 + e8 - e6 - e2);
        const float h02 = 0.25f * (a1v + c7v - a7v - c1v);

        const float c00 = h11 * h22 - h12 * h12;
        const float c01 = h01 * h22 - h12 * h02;
        const float c02 = h01 * h12 - h11 * h02;
        const float det = h00 * c00 - h01 * c01 + h02 * c02;

        const float t1 = gy * h22 - h12 * gs;
        const float t2 = gy * h12 - h11 * gs;
        const float t3 = h01 * gs - gy * h02;

        const float inv = 1.0f / det;
        const float sx = (gx * c00 - h01 * t1 + h02 * t2) * inv;
        const float sy = (h00 * t1 - gx * c01 + h02 * t3) * inv;
        const float ss = (h00 * (h11 * gs - h12 * gy) - h01 * t3 + gx * c02) * inv;

        float d0 = -sx, d1 = -sy, d2 = -ss;
        const float far = fmaxf(fmaxf(fabsf(d0), fabsf(d1)), fabsf(d2));
        if (far > 0.7f) { d0 = 0.0f; d1 = 0.0f; d2 = 0.0f; }

        const float ry = cc + 0.5f * (gx * d0 + gy * d1 + gs * d2) + 10.0f;

        const size_t innq = (size_t)(d * HH + hq) * WW + wq;
        o0[innq] = (float)d  + d2;
        o1[innq] = (float)hq + d1;
        o2[innq] = (float)wq + d0;
        oy[innq] = ry;
    }
}

extern "C" void kernel_launch(void* const* d_in, const int* in_sizes, int n_in,
                              void* d_out, int out_size) {
    const float* x = (const float*)d_in[0];
    float* out = (float*)d_out;
    const int total_threads = BB * DD * (HH / 2) * (WW / 4);   // 655,360
    const int block = 256;
    const int grid = total_threads / block;                    // 2,560
    quadinterp3d_kernel<<<grid, block>>>(x, out);
}